// round 3
// baseline (speedup 1.0000x reference)
#include <cuda_runtime.h>
#include <math.h>
#include <stdint.h>

#define NB 8
#define NC 512
#define HIN 32
#define HT 65
#define HO 64

// ---------------- scratch (device globals; no allocations allowed) ----------
__device__ float g_xs[NB * NC * HIN * HIN];   // style-scaled input
__device__ float g_t1[NB * NC * HT * HT];     // conv1 (transpose) output 65x65
__device__ float g_a1[NB * NC * HO * HO];     // blur+noise+lrelu, pre-scaled by s2
__device__ float g_a2[NB * NC * HO * HO];     // conv2 output, pre-scaled by s_rgb
__device__ float g_d1[NB * NC];
__device__ float g_d2[NB * NC];

struct TapList { int dy[9]; int dx[9]; int wo[9]; };

__device__ __forceinline__ uint32_t f2tf32(float x) {
    uint32_t r;
    asm("cvt.rna.tf32.f32 %0, %1;" : "=r"(r) : "f"(x));
    return r;
}

__device__ __forceinline__ void mma_tf32(float* d, const uint32_t* a, const uint32_t* b) {
    asm volatile(
        "mma.sync.aligned.m16n8k8.row.col.f32.tf32.tf32.f32 "
        "{%0,%1,%2,%3}, {%4,%5,%6,%7}, {%8,%9}, {%0,%1,%2,%3};\n"
        : "+f"(d[0]), "+f"(d[1]), "+f"(d[2]), "+f"(d[3])
        : "r"(a[0]), "r"(a[1]), "r"(a[2]), "r"(a[3]), "r"(b[0]), "r"(b[1]));
}

// ---------------- K0: demodulation factors ----------------------------------
__global__ void k_demod(const float* __restrict__ w, const float* __restrict__ s,
                        float* __restrict__ d, float scale) {
    int b  = blockIdx.x >> 9;
    int co = blockIdx.x & 511;
    const float* wr = w + co * 4608;
    const float* sr = s + b * 512;
    float acc = 0.f;
    for (int k = threadIdx.x; k < 4608; k += 128) {
        int ci = k / 9;
        float t = wr[k] * sr[ci];
        acc += t * t;
    }
    __shared__ float red[128];
    red[threadIdx.x] = acc;
    __syncthreads();
    for (int off = 64; off > 0; off >>= 1) {
        if (threadIdx.x < off) red[threadIdx.x] += red[threadIdx.x + off];
        __syncthreads();
    }
    if (threadIdx.x == 0)
        d[b * 512 + co] = scale * rsqrtf(scale * scale * red[0] + 1e-8f);
}

// ---------------- K_scale: xs = x * s1[b,c] ---------------------------------
__global__ void k_scale_x(const float* __restrict__ x, const float* __restrict__ s1,
                          float* __restrict__ xs) {
    int i = blockIdx.x * 256 + threadIdx.x;
    if (i < NB * NC * HIN * HIN) {
        int c = (i >> 10) & 511;
        int b = i >> 19;
        xs[i] = x[i] * s1[b * 512 + c];
    }
}

// ---------------- implicit-GEMM conv on TF32 tensor cores -------------------
// M=512(cout) x N=pixels x K=512*NTAPS. Block 128x128xBK16, 8 warps 2x4,
// warp tile 64x32 via m16n8k8 tf32 mma. 2-stage smem double buffering.
// EPI 0: out = acc * dmod   (conv1 phases -> strided write into 65x65 buffer)
// EPI 1: out = lrelu(acc*dmod + nw*noise + bias)*sqrt2 * snext  (conv2)
template <int NTAPS, int EPI>
__global__ __launch_bounds__(256, 2) void conv_mma(
    const float* __restrict__ in, const float* __restrict__ wgt,
    float* __restrict__ out,
    const float* __restrict__ dmod,
    const float* __restrict__ noise, const float* __restrict__ nwp,
    const float* __restrict__ bias, const float* __restrict__ snext,
    int IH, int IW, int GH, int GW,
    int out_bstride, int out_cstride, int out_ys, int out_xs, int out_off,
    TapList taps)
{
    const int BK = 16, LD = 136;
    __shared__ uint32_t As[2][BK * LD];
    __shared__ uint32_t Bs[2][BK * LD];

    int tid  = threadIdx.x;
    int lane = tid & 31, warp = tid >> 5;
    int wm = warp & 1, wn = warp >> 1;       // warp grid 2(M) x 4(N)
    int mbase = wm * 64, nbase = wn * 32;
    int kq = lane & 3, rq = lane >> 2;

    int b   = blockIdx.z;
    int co0 = blockIdx.y * 128;
    int n0  = blockIdx.x * 128;
    int GHW = GH * GW;
    const int K   = 512 * NTAPS;
    const int NIT = K / BK;

    const float* inb = in + (size_t)b * 512 * IH * IW;

    // A loads: m-fast (per-thread fixed output channel)
    int am  = tid & 127;
    int akl = tid >> 7;                        // element l has kl = akl + 2l
    const float* wrow = wgt + (size_t)(co0 + am) * 4608;

    // B loads: n-fast (per-thread fixed pixel)
    int nl  = tid & 127;
    int bkl = tid >> 7;
    int ng  = n0 + nl;
    int oy, ox;
    if (ng < GHW) { oy = ng / GW; ox = ng - oy * GW; }
    else          { oy = -100000; ox = 0; }

    float acc[4][4][4];
#pragma unroll
    for (int i = 0; i < 4; i++)
#pragma unroll
        for (int j = 0; j < 4; j++)
#pragma unroll
            for (int r = 0; r < 4; r++) acc[i][j][r] = 0.f;

    float pa[8], pb[8];

    auto loadAB = [&](int kb) {
#pragma unroll
        for (int l = 0; l < 8; l++) {
            int kg = kb + akl + 2 * l;
            int ci = kg / NTAPS;
            int t  = kg - ci * NTAPS;
            pa[l] = wrow[ci * 9 + taps.wo[t]];
        }
#pragma unroll
        for (int l = 0; l < 8; l++) {
            int kg = kb + bkl + 2 * l;
            int ci = kg / NTAPS;
            int t  = kg - ci * NTAPS;
            int iy = oy + taps.dy[t];
            int ix = ox + taps.dx[t];
            float v = 0.f;
            if (iy >= 0 && iy < IH && ix >= 0 && ix < IW)
                v = __ldg(&inb[(size_t)(ci * IH + iy) * IW + ix]);
            pb[l] = v;
        }
    };
    auto storeAB = [&](int st) {
#pragma unroll
        for (int l = 0; l < 8; l++) As[st][(akl + 2 * l) * LD + am] = f2tf32(pa[l]);
#pragma unroll
        for (int l = 0; l < 8; l++) Bs[st][(bkl + 2 * l) * LD + nl] = f2tf32(pb[l]);
    };

    loadAB(0);
    storeAB(0);
    __syncthreads();

    for (int it = 0; it < NIT; it++) {
        int st = it & 1;
        if (it + 1 < NIT) loadAB((it + 1) * BK);

        const uint32_t* Ap = As[st];
        const uint32_t* Bp = Bs[st];
#pragma unroll
        for (int ks = 0; ks < 2; ks++) {
            uint32_t af[4][4], bf[4][2];
#pragma unroll
            for (int mt = 0; mt < 4; mt++) {
                int r = mbase + mt * 16 + rq;
                af[mt][0] = Ap[(ks * 8 + kq) * LD + r];
                af[mt][1] = Ap[(ks * 8 + kq) * LD + r + 8];
                af[mt][2] = Ap[(ks * 8 + kq + 4) * LD + r];
                af[mt][3] = Ap[(ks * 8 + kq + 4) * LD + r + 8];
            }
#pragma unroll
            for (int nt = 0; nt < 4; nt++) {
                int c = nbase + nt * 8 + rq;
                bf[nt][0] = Bp[(ks * 8 + kq) * LD + c];
                bf[nt][1] = Bp[(ks * 8 + kq + 4) * LD + c];
            }
#pragma unroll
            for (int mt = 0; mt < 4; mt++)
#pragma unroll
                for (int nt = 0; nt < 4; nt++)
                    mma_tf32(acc[mt][nt], af[mt], bf[nt]);
        }

        if (it + 1 < NIT) storeAB((it + 1) & 1);
        __syncthreads();
    }

    // ---- epilogue ----
    const float SQRT2 = 1.41421356237309515f;
    float* outb = out + (size_t)b * out_bstride;
    float nwv = (EPI == 1) ? nwp[0] : 0.f;
#pragma unroll
    for (int mt = 0; mt < 4; mt++) {
#pragma unroll
        for (int half = 0; half < 2; half++) {
            int co = co0 + mbase + mt * 16 + rq + half * 8;
            float dm = dmod[b * 512 + co];
            float bi = (EPI == 1) ? bias[co] : 0.f;
            float sn = (EPI == 1) ? snext[b * 512 + co] : 0.f;
#pragma unroll
            for (int nt = 0; nt < 4; nt++) {
#pragma unroll
                for (int j = 0; j < 2; j++) {
                    int n = n0 + nbase + nt * 8 + kq * 2 + j;
                    if (n < GHW) {
                        int oyp = n / GW;
                        int oxp = n - oyp * GW;
                        float v = acc[mt][nt][half * 2 + j] * dm;
                        if (EPI == 1) {
                            v += nwv * noise[b * GHW + n] + bi;
                            v = (v >= 0.f ? v : 0.2f * v) * SQRT2;
                            v *= sn;
                        }
                        outb[(size_t)co * out_cstride + oyp * out_ys + oxp * out_xs + out_off] = v;
                    }
                }
            }
        }
    }
}

// ---------------- K2: blur 4x4 + noise + bias + lrelu + s2 fold -------------
__global__ void k_blur(const float* __restrict__ t1, const float* __restrict__ n1,
                       const float* __restrict__ nw1, const float* __restrict__ b1,
                       const float* __restrict__ s2, float* __restrict__ a1) {
    int pix = blockIdx.x * 256 + threadIdx.x;  // 0..4095
    int c = blockIdx.y, b = blockIdx.z;
    int y = pix >> 6, x = pix & 63;
    const float kv[4] = {1.f, 3.f, 3.f, 1.f};
    const float* tb = t1 + (size_t)(b * 512 + c) * (HT * HT);
    float acc = 0.f;
#pragma unroll
    for (int p = 0; p < 4; p++) {
        int ty = y + p - 1;
        if (ty < 0 || ty >= HT) continue;
        float row = 0.f;
#pragma unroll
        for (int q = 0; q < 4; q++) {
            int tx = x + q - 1;
            if (tx < 0 || tx >= HT) continue;
            row += tb[ty * HT + tx] * kv[q];
        }
        acc += row * kv[p];
    }
    acc *= (1.f / 16.f);
    float v = acc + nw1[0] * n1[b * 4096 + pix] + b1[c];
    v = (v >= 0.f ? v : 0.2f * v) * 1.41421356237309515f;
    a1[(size_t)(b * 512 + c) * 4096 + pix] = v * s2[b * 512 + c];
}

// ---------------- K4: ToRGB (1x1, no demod) + bias + skip upfirdn up=2 ------
// 64 pixels/block, 4 channel groups of 128, smem reduce. Grid (64, NB).
__global__ void k_torgb(const float* __restrict__ a2, const float* __restrict__ wrgb,
                        const float* __restrict__ brgb, const float* __restrict__ skip,
                        float* __restrict__ outp) {
    __shared__ float sw[1536];
    __shared__ float red[3][256];
    int tid = threadIdx.x;
    int b = blockIdx.y;
    const float srgb = 0.044194173824159216f;  // 1/sqrt(512)
    for (int i = tid; i < 1536; i += 256) sw[i] = wrgb[i] * srgb;
    __syncthreads();

    int p = tid & 63;
    int g = tid >> 6;
    int pix = blockIdx.x * 64 + p;
    const float* ab = a2 + (size_t)b * 512 * 4096 + pix;
    float acc0 = 0.f, acc1 = 0.f, acc2 = 0.f;
#pragma unroll 8
    for (int c = g * 128; c < g * 128 + 128; c++) {
        float v = ab[(size_t)c * 4096];
        acc0 += sw[c] * v;
        acc1 += sw[512 + c] * v;
        acc2 += sw[1024 + c] * v;
    }
    red[0][tid] = acc0; red[1][tid] = acc1; red[2][tid] = acc2;
    __syncthreads();

    if (g == 0) {
        int y = pix >> 6, x = pix & 63;
        int iy0, iy1, ix0, ix1;
        float wy0, wy1, wx0, wx1;
        if ((y & 1) == 0) { iy0 = y / 2 - 1;   wy0 = 1.f; iy1 = y / 2;       wy1 = 3.f; }
        else              { iy0 = (y - 1) / 2; wy0 = 3.f; iy1 = (y + 1) / 2; wy1 = 1.f; }
        if ((x & 1) == 0) { ix0 = x / 2 - 1;   wx0 = 1.f; ix1 = x / 2;       wx1 = 3.f; }
        else              { ix0 = (x - 1) / 2; wx0 = 3.f; ix1 = (x + 1) / 2; wx1 = 1.f; }

#pragma unroll
        for (int o = 0; o < 3; o++) {
            float acc = red[o][p] + red[o][p + 64] + red[o][p + 128] + red[o][p + 192];
            const float* sb = skip + (size_t)(b * 3 + o) * 1024;
            float s = 0.f;
            if (iy0 >= 0 && iy0 < 32) {
                if (ix0 >= 0 && ix0 < 32) s += sb[iy0 * 32 + ix0] * wy0 * wx0;
                if (ix1 >= 0 && ix1 < 32) s += sb[iy0 * 32 + ix1] * wy0 * wx1;
            }
            if (iy1 >= 0 && iy1 < 32) {
                if (ix0 >= 0 && ix0 < 32) s += sb[iy1 * 32 + ix0] * wy1 * wx0;
                if (ix1 >= 0 && ix1 < 32) s += sb[iy1 * 32 + ix1] * wy1 * wx1;
            }
            s *= (1.f / 16.f);
            outp[(size_t)(b * 3 + o) * 4096 + pix] = acc + brgb[o] + s;
        }
    }
}

// ---------------- launch -----------------------------------------------------
extern "C" void kernel_launch(void* const* d_in, const int* in_sizes, int n_in,
                              void* d_out, int out_size) {
    const float* x    = (const float*)d_in[0];
    const float* skip = (const float*)d_in[1];
    const float* w1   = (const float*)d_in[2];
    const float* b1   = (const float*)d_in[3];
    const float* s1   = (const float*)d_in[4];
    const float* nw1  = (const float*)d_in[5];
    const float* n1   = (const float*)d_in[6];
    const float* w2   = (const float*)d_in[7];
    const float* b2   = (const float*)d_in[8];
    const float* s2   = (const float*)d_in[9];
    const float* nw2  = (const float*)d_in[10];
    const float* n2   = (const float*)d_in[11];
    const float* wrgb = (const float*)d_in[12];
    const float* brgb = (const float*)d_in[13];
    const float* srgb = (const float*)d_in[14];
    float* outp = (float*)d_out;

    float *xs, *t1, *a1, *a2, *d1, *d2;
    cudaGetSymbolAddress((void**)&xs, g_xs);
    cudaGetSymbolAddress((void**)&t1, g_t1);
    cudaGetSymbolAddress((void**)&a1, g_a1);
    cudaGetSymbolAddress((void**)&a2, g_a2);
    cudaGetSymbolAddress((void**)&d1, g_d1);
    cudaGetSymbolAddress((void**)&d2, g_d2);

    const float sc = 1.0f / sqrtf(512.0f * 9.0f);

    k_scale_x<<<(NB * NC * HIN * HIN + 255) / 256, 256>>>(x, s1, xs);
    k_demod<<<NB * NC, 128>>>(w1, s1, d1, sc);
    k_demod<<<NB * NC, 128>>>(w2, s2, d2, sc);

    int bstride1 = NC * HT * HT;

    {   // phase (0,0): 4 taps, grid 33x33
        TapList tp = {{0, 0, -1, -1, 0, 0, 0, 0, 0},
                      {0, -1, 0, -1, 0, 0, 0, 0, 0},
                      {0, 2, 6, 8, 0, 0, 0, 0, 0}};
        conv_mma<4, 0><<<dim3((33 * 33 + 127) / 128, 4, NB), 256>>>(
            xs, w1, t1, d1, nullptr, nullptr, nullptr, nullptr,
            HIN, HIN, 33, 33, bstride1, HT * HT, 2 * HT, 2, 0 * HT + 0, tp);
    }
    {   // phase (0,1): 2 taps
        TapList tp = {{0, -1, 0, 0, 0, 0, 0, 0, 0},
                      {0, 0, 0, 0, 0, 0, 0, 0, 0},
                      {1, 7, 0, 0, 0, 0, 0, 0, 0}};
        conv_mma<2, 0><<<dim3((33 * 32 + 127) / 128, 4, NB), 256>>>(
            xs, w1, t1, d1, nullptr, nullptr, nullptr, nullptr,
            HIN, HIN, 33, 32, bstride1, HT * HT, 2 * HT, 2, 0 * HT + 1, tp);
    }
    {   // phase (1,0): 2 taps
        TapList tp = {{0, 0, 0, 0, 0, 0, 0, 0, 0},
                      {0, -1, 0, 0, 0, 0, 0, 0, 0},
                      {3, 5, 0, 0, 0, 0, 0, 0, 0}};
        conv_mma<2, 0><<<dim3((32 * 33 + 127) / 128, 4, NB), 256>>>(
            xs, w1, t1, d1, nullptr, nullptr, nullptr, nullptr,
            HIN, HIN, 32, 33, bstride1, HT * HT, 2 * HT, 2, 1 * HT + 0, tp);
    }
    {   // phase (1,1): 1 tap
        TapList tp = {{0, 0, 0, 0, 0, 0, 0, 0, 0},
                      {0, 0, 0, 0, 0, 0, 0, 0, 0},
                      {4, 0, 0, 0, 0, 0, 0, 0, 0}};
        conv_mma<1, 0><<<dim3((32 * 32 + 127) / 128, 4, NB), 256>>>(
            xs, w1, t1, d1, nullptr, nullptr, nullptr, nullptr,
            HIN, HIN, 32, 32, bstride1, HT * HT, 2 * HT, 2, 1 * HT + 1, tp);
    }

    k_blur<<<dim3(16, NC, NB), 256>>>(t1, n1, nw1, b1, s2, a1);

    {   // conv2: 3x3 same, 9 taps
        TapList tp = {{-1, -1, -1, 0, 0, 0, 1, 1, 1},
                      {-1, 0, 1, -1, 0, 1, -1, 0, 1},
                      {0, 1, 2, 3, 4, 5, 6, 7, 8}};
        conv_mma<9, 1><<<dim3((HO * HO + 127) / 128, 4, NB), 256>>>(
            a1, w2, a2, d2, n2, nw2, b2, srgb,
            HO, HO, HO, HO, NC * HO * HO, HO * HO, HO, 1, 0, tp);
    }

    k_torgb<<<dim3(64, NB), 256>>>(a2, wrgb, brgb, skip, outp);
}

// round 4
// speedup vs baseline: 1.5996x; 1.5996x over previous
#include <cuda_runtime.h>
#include <math.h>
#include <stdint.h>

#define NB 8
#define NC 512
#define HIN 32
#define HT 65
#define HO 64

// ---------------- scratch (device globals; no allocations allowed) ----------
__device__ float g_xs[NB * NC * HIN * HIN];   // style-scaled input
__device__ float g_t1[NB * NC * HT * HT];     // conv1 (transpose) output 65x65
__device__ float g_a1[NB * NC * HO * HO];     // blur+noise+lrelu, pre-scaled by s2
__device__ float g_a2[NB * NC * HO * HO];     // conv2 output, pre-scaled by s_rgb
__device__ float g_d1[NB * NC];
__device__ float g_d2[NB * NC];

struct TapList { int dy[9]; int dx[9]; int wo[9]; };

__device__ __forceinline__ uint32_t f2tf32(float x) {
    uint32_t r;
    asm("cvt.rna.tf32.f32 %0, %1;" : "=r"(r) : "f"(x));
    return r;
}

__device__ __forceinline__ void mma_tf32(float* d, const uint32_t* a, const uint32_t* b) {
    asm volatile(
        "mma.sync.aligned.m16n8k8.row.col.f32.tf32.tf32.f32 "
        "{%0,%1,%2,%3}, {%4,%5,%6,%7}, {%8,%9}, {%0,%1,%2,%3};\n"
        : "+f"(d[0]), "+f"(d[1]), "+f"(d[2]), "+f"(d[3])
        : "r"(a[0]), "r"(a[1]), "r"(a[2]), "r"(a[3]), "r"(b[0]), "r"(b[1]));
}

// ---------------- K0: demodulation factors ----------------------------------
__global__ void k_demod(const float* __restrict__ w, const float* __restrict__ s,
                        float* __restrict__ d, float scale) {
    int b  = blockIdx.x >> 9;
    int co = blockIdx.x & 511;
    const float* wr = w + co * 4608;
    const float* sr = s + b * 512;
    float acc = 0.f;
    for (int k = threadIdx.x; k < 4608; k += 128) {
        int ci = k / 9;
        float t = wr[k] * sr[ci];
        acc += t * t;
    }
    __shared__ float red[128];
    red[threadIdx.x] = acc;
    __syncthreads();
    for (int off = 64; off > 0; off >>= 1) {
        if (threadIdx.x < off) red[threadIdx.x] += red[threadIdx.x + off];
        __syncthreads();
    }
    if (threadIdx.x == 0)
        d[b * 512 + co] = scale * rsqrtf(scale * scale * red[0] + 1e-8f);
}

// ---------------- K_scale: xs = x * s1[b,c] ---------------------------------
__global__ void k_scale_x(const float* __restrict__ x, const float* __restrict__ s1,
                          float* __restrict__ xs) {
    int i = blockIdx.x * 256 + threadIdx.x;
    if (i < NB * NC * HIN * HIN) {
        int c = (i >> 10) & 511;
        int b = i >> 19;
        xs[i] = x[i] * s1[b * 512 + c];
    }
}

// ---------------- implicit-GEMM conv on TF32 tensor cores -------------------
// Block 128x128xBK16, 8 warps 2x4, warp tile 64x32 via m16n8k8 tf32 mma.
// A smem is FRAGMENT-MAJOR: element (m,k) of the tile lives at
//   idx = k8*1024 + mblk*128 + lane*4 + e
//   where mblk=m>>4, mr=m&15, rq=mr&7, eb0=mr>>3, k8=k>>3, kq=k&3, eb1=(k>>2)&1,
//         lane=rq*4+kq, e=eb0+2*eb1
// so each thread's 4 mma-A operands are one LDS.128 (conflict-free).
// B smem is row-major LD=136 (fragment loads 8x LDS.32, conflict-free).
template <int NTAPS, int EPI>
__global__ __launch_bounds__(256, 2) void conv_mma(
    const float* __restrict__ in, const float* __restrict__ wgt,
    float* __restrict__ out,
    const float* __restrict__ dmod,
    const float* __restrict__ noise, const float* __restrict__ nwp,
    const float* __restrict__ bias, const float* __restrict__ snext,
    int IH, int IW, int GH, int GW,
    int out_bstride, int out_cstride, int out_ys, int out_xs, int out_off,
    TapList taps)
{
    const int BK = 16, LDB = 136;
    __shared__ uint32_t As[2][2048];        // 2 k8-blocks * 8 mblk * 32 lanes * 4
    __shared__ uint32_t Bs[2][BK * LDB];

    int tid  = threadIdx.x;
    int lane = tid & 31, warp = tid >> 5;
    int wm = warp & 1, wn = warp >> 1;       // warp grid 2(M) x 4(N)
    int nbase = wn * 32;
    int kq = lane & 3, rq = lane >> 2;

    int b   = blockIdx.z;
    int co0 = blockIdx.y * 128;
    int n0  = blockIdx.x * 128;
    int GHW = GH * GW;
    const int K   = 512 * NTAPS;
    const int NIT = K / BK;

    const float* inb = in + (size_t)b * 512 * IH * IW;

    // ---- A loads: lane-contiguous k within a weight row (coalesced) ----
    int akm = tid >> 4;                      // row-in-tile base (0..15), rows akm+16*l
    int akk = tid & 15;                      // k within BK tile
    const float* wbase = wgt + (size_t)(co0 + akm) * 4608;
    // fragment-store address for this thread (fixed except mblk=l)
    int a_st = (akk >> 3) * 1024 + (((akm & 7) * 4 + (akk & 3)) * 4)
             + (akm >> 3) + 2 * ((akk >> 2) & 1);

    // ---- B loads: n-fast (per-thread fixed pixel) ----
    int nl  = tid & 127;
    int bkl = tid >> 7;
    int ng  = n0 + nl;
    int oy, ox;
    if (ng < GHW) { oy = ng / GW; ox = ng - oy * GW; }
    else          { oy = -100000; ox = 0; }

    float acc[4][4][4];
#pragma unroll
    for (int i = 0; i < 4; i++)
#pragma unroll
        for (int j = 0; j < 4; j++)
#pragma unroll
            for (int r = 0; r < 4; r++) acc[i][j][r] = 0.f;

    float pa[8], pb[8];

    auto loadAB = [&](int kb) {
        int kg = kb + akk;
        int ci = kg / NTAPS;
        int t  = kg - ci * NTAPS;
        int aoff = ci * 9 + taps.wo[t];
#pragma unroll
        for (int l = 0; l < 8; l++)
            pa[l] = wbase[(size_t)(16 * l) * 4608 + aoff];
#pragma unroll
        for (int l = 0; l < 8; l++) {
            int kg2 = kb + bkl + 2 * l;
            int ci2 = kg2 / NTAPS;
            int t2  = kg2 - ci2 * NTAPS;
            int iy = oy + taps.dy[t2];
            int ix = ox + taps.dx[t2];
            float v = 0.f;
            if (iy >= 0 && iy < IH && ix >= 0 && ix < IW)
                v = __ldg(&inb[(size_t)(ci2 * IH + iy) * IW + ix]);
            pb[l] = v;
        }
    };
    auto storeAB = [&](int st) {
#pragma unroll
        for (int l = 0; l < 8; l++) As[st][a_st + l * 128] = f2tf32(pa[l]);
#pragma unroll
        for (int l = 0; l < 8; l++) Bs[st][(bkl + 2 * l) * LDB + nl] = f2tf32(pb[l]);
    };

    loadAB(0);
    storeAB(0);
    __syncthreads();

    for (int it = 0; it < NIT; it++) {
        int st = it & 1;
        if (it + 1 < NIT) loadAB((it + 1) * BK);

        const uint32_t* Ap = As[st];
        const uint32_t* Bp = Bs[st];
#pragma unroll
        for (int ks = 0; ks < 2; ks++) {
            uint32_t af[4][4], bf[4][2];
#pragma unroll
            for (int mt = 0; mt < 4; mt++) {
                const uint4 v = *reinterpret_cast<const uint4*>(
                    &Ap[ks * 1024 + (wm * 4 + mt) * 128 + lane * 4]);
                af[mt][0] = v.x; af[mt][1] = v.y; af[mt][2] = v.z; af[mt][3] = v.w;
            }
#pragma unroll
            for (int nt = 0; nt < 4; nt++) {
                int c = nbase + nt * 8 + rq;
                bf[nt][0] = Bp[(ks * 8 + kq) * LDB + c];
                bf[nt][1] = Bp[(ks * 8 + kq + 4) * LDB + c];
            }
#pragma unroll
            for (int mt = 0; mt < 4; mt++)
#pragma unroll
                for (int nt = 0; nt < 4; nt++)
                    mma_tf32(acc[mt][nt], af[mt], bf[nt]);
        }

        if (it + 1 < NIT) storeAB((it + 1) & 1);
        __syncthreads();
    }

    // ---- epilogue (acc layout: rows rq+8*half, cols kq*2+j within 16x8 tile) ----
    const float SQRT2 = 1.41421356237309515f;
    float* outb = out + (size_t)b * out_bstride;
    float nwv = (EPI == 1) ? nwp[0] : 0.f;
    int mbase = wm * 64;
#pragma unroll
    for (int mt = 0; mt < 4; mt++) {
#pragma unroll
        for (int half = 0; half < 2; half++) {
            int co = co0 + mbase + mt * 16 + rq + half * 8;
            float dm = dmod[b * 512 + co];
            float bi = (EPI == 1) ? bias[co] : 0.f;
            float sn = (EPI == 1) ? snext[b * 512 + co] : 0.f;
#pragma unroll
            for (int nt = 0; nt < 4; nt++) {
#pragma unroll
                for (int j = 0; j < 2; j++) {
                    int n = n0 + nbase + nt * 8 + kq * 2 + j;
                    if (n < GHW) {
                        int oyp = n / GW;
                        int oxp = n - oyp * GW;
                        float v = acc[mt][nt][half * 2 + j] * dm;
                        if (EPI == 1) {
                            v += nwv * noise[b * GHW + n] + bi;
                            v = (v >= 0.f ? v : 0.2f * v) * SQRT2;
                            v *= sn;
                        }
                        outb[(size_t)co * out_cstride + oyp * out_ys + oxp * out_xs + out_off] = v;
                    }
                }
            }
        }
    }
}

// ---------------- K2: blur 4x4 (separable, smem-tiled) + noise + lrelu + s2 -
// One block per (channel, batch). Halo tile 67x67 of t1 (rows/cols -1..65).
__global__ __launch_bounds__(256) void k_blur(
    const float* __restrict__ t1, const float* __restrict__ n1,
    const float* __restrict__ nw1, const float* __restrict__ b1,
    const float* __restrict__ s2, float* __restrict__ a1)
{
    __shared__ float raw[67 * 68];   // [row -1..65][col -1..65], LD=68
    __shared__ float tmp[67 * 64];   // H-pass result: [row -1..65][x 0..63]
    int tid = threadIdx.x;
    int c = blockIdx.x, b = blockIdx.y;
    const float* tb = t1 + (size_t)(b * 512 + c) * (HT * HT);

    // load halo tile
    for (int i = tid; i < 67 * 67; i += 256) {
        int rr = i / 67, cc = i - rr * 67;
        int ty = rr - 1, tx = cc - 1;
        float v = 0.f;
        if (ty >= 0 && ty < HT && tx >= 0 && tx < HT) v = tb[ty * HT + tx];
        raw[rr * 68 + cc] = v;
    }
    __syncthreads();

    // horizontal pass: tmp[r][x] = 1*raw[r][x] + 3*raw[r][x+1] + 3*raw[r][x+2] + 1*raw[r][x+3]
    for (int i = tid; i < 67 * 64; i += 256) {
        int r = i >> 6, x = i & 63;
        const float* rp = &raw[r * 68 + x];
        tmp[i] = rp[0] + 3.f * rp[1] + 3.f * rp[2] + rp[3];
    }
    __syncthreads();

    // vertical pass + noise + bias + lrelu + s2
    float nwv = nw1[0];
    float bi  = b1[c];
    float s2v = s2[b * 512 + c];
    float* ap = a1 + (size_t)(b * 512 + c) * 4096;
    const float* np = n1 + (size_t)b * 4096;
    for (int pix = tid; pix < 4096; pix += 256) {
        int y = pix >> 6, x = pix & 63;
        float acc = tmp[y * 64 + x] + 3.f * tmp[(y + 1) * 64 + x]
                  + 3.f * tmp[(y + 2) * 64 + x] + tmp[(y + 3) * 64 + x];
        acc *= (1.f / 16.f);
        float v = acc + nwv * np[pix] + bi;
        v = (v >= 0.f ? v : 0.2f * v) * 1.41421356237309515f;
        ap[pix] = v * s2v;
    }
}

// ---------------- K4: ToRGB (1x1, no demod) + bias + skip upfirdn up=2 ------
__global__ void k_torgb(const float* __restrict__ a2, const float* __restrict__ wrgb,
                        const float* __restrict__ brgb, const float* __restrict__ skip,
                        float* __restrict__ outp) {
    __shared__ float sw[1536];
    __shared__ float red[3][256];
    int tid = threadIdx.x;
    int b = blockIdx.y;
    const float srgb = 0.044194173824159216f;  // 1/sqrt(512)
    for (int i = tid; i < 1536; i += 256) sw[i] = wrgb[i] * srgb;
    __syncthreads();

    int p = tid & 63;
    int g = tid >> 6;
    int pix = blockIdx.x * 64 + p;
    const float* ab = a2 + (size_t)b * 512 * 4096 + pix;
    float acc0 = 0.f, acc1 = 0.f, acc2 = 0.f;
#pragma unroll 8
    for (int c = g * 128; c < g * 128 + 128; c++) {
        float v = ab[(size_t)c * 4096];
        acc0 += sw[c] * v;
        acc1 += sw[512 + c] * v;
        acc2 += sw[1024 + c] * v;
    }
    red[0][tid] = acc0; red[1][tid] = acc1; red[2][tid] = acc2;
    __syncthreads();

    if (g == 0) {
        int y = pix >> 6, x = pix & 63;
        int iy0, iy1, ix0, ix1;
        float wy0, wy1, wx0, wx1;
        if ((y & 1) == 0) { iy0 = y / 2 - 1;   wy0 = 1.f; iy1 = y / 2;       wy1 = 3.f; }
        else              { iy0 = (y - 1) / 2; wy0 = 3.f; iy1 = (y + 1) / 2; wy1 = 1.f; }
        if ((x & 1) == 0) { ix0 = x / 2 - 1;   wx0 = 1.f; ix1 = x / 2;       wx1 = 3.f; }
        else              { ix0 = (x - 1) / 2; wx0 = 3.f; ix1 = (x + 1) / 2; wx1 = 1.f; }

#pragma unroll
        for (int o = 0; o < 3; o++) {
            float acc = red[o][p] + red[o][p + 64] + red[o][p + 128] + red[o][p + 192];
            const float* sb = skip + (size_t)(b * 3 + o) * 1024;
            float s = 0.f;
            if (iy0 >= 0 && iy0 < 32) {
                if (ix0 >= 0 && ix0 < 32) s += sb[iy0 * 32 + ix0] * wy0 * wx0;
                if (ix1 >= 0 && ix1 < 32) s += sb[iy0 * 32 + ix1] * wy0 * wx1;
            }
            if (iy1 >= 0 && iy1 < 32) {
                if (ix0 >= 0 && ix0 < 32) s += sb[iy1 * 32 + ix0] * wy1 * wx0;
                if (ix1 >= 0 && ix1 < 32) s += sb[iy1 * 32 + ix1] * wy1 * wx1;
            }
            s *= (1.f / 16.f);
            outp[(size_t)(b * 3 + o) * 4096 + pix] = acc + brgb[o] + s;
        }
    }
}

// ---------------- launch -----------------------------------------------------
extern "C" void kernel_launch(void* const* d_in, const int* in_sizes, int n_in,
                              void* d_out, int out_size) {
    const float* x    = (const float*)d_in[0];
    const float* skip = (const float*)d_in[1];
    const float* w1   = (const float*)d_in[2];
    const float* b1   = (const float*)d_in[3];
    const float* s1   = (const float*)d_in[4];
    const float* nw1  = (const float*)d_in[5];
    const float* n1   = (const float*)d_in[6];
    const float* w2   = (const float*)d_in[7];
    const float* b2   = (const float*)d_in[8];
    const float* s2   = (const float*)d_in[9];
    const float* nw2  = (const float*)d_in[10];
    const float* n2   = (const float*)d_in[11];
    const float* wrgb = (const float*)d_in[12];
    const float* brgb = (const float*)d_in[13];
    const float* srgb = (const float*)d_in[14];
    float* outp = (float*)d_out;

    float *xs, *t1, *a1, *a2, *d1, *d2;
    cudaGetSymbolAddress((void**)&xs, g_xs);
    cudaGetSymbolAddress((void**)&t1, g_t1);
    cudaGetSymbolAddress((void**)&a1, g_a1);
    cudaGetSymbolAddress((void**)&a2, g_a2);
    cudaGetSymbolAddress((void**)&d1, g_d1);
    cudaGetSymbolAddress((void**)&d2, g_d2);

    const float sc = 1.0f / sqrtf(512.0f * 9.0f);

    k_scale_x<<<(NB * NC * HIN * HIN + 255) / 256, 256>>>(x, s1, xs);
    k_demod<<<NB * NC, 128>>>(w1, s1, d1, sc);
    k_demod<<<NB * NC, 128>>>(w2, s2, d2, sc);

    int bstride1 = NC * HT * HT;

    {   // phase (0,0): 4 taps, grid 33x33
        TapList tp = {{0, 0, -1, -1, 0, 0, 0, 0, 0},
                      {0, -1, 0, -1, 0, 0, 0, 0, 0},
                      {0, 2, 6, 8, 0, 0, 0, 0, 0}};
        conv_mma<4, 0><<<dim3((33 * 33 + 127) / 128, 4, NB), 256>>>(
            xs, w1, t1, d1, nullptr, nullptr, nullptr, nullptr,
            HIN, HIN, 33, 33, bstride1, HT * HT, 2 * HT, 2, 0 * HT + 0, tp);
    }
    {   // phase (0,1): 2 taps
        TapList tp = {{0, -1, 0, 0, 0, 0, 0, 0, 0},
                      {0, 0, 0, 0, 0, 0, 0, 0, 0},
                      {1, 7, 0, 0, 0, 0, 0, 0, 0}};
        conv_mma<2, 0><<<dim3((33 * 32 + 127) / 128, 4, NB), 256>>>(
            xs, w1, t1, d1, nullptr, nullptr, nullptr, nullptr,
            HIN, HIN, 33, 32, bstride1, HT * HT, 2 * HT, 2, 0 * HT + 1, tp);
    }
    {   // phase (1,0): 2 taps
        TapList tp = {{0, 0, 0, 0, 0, 0, 0, 0, 0},
                      {0, -1, 0, 0, 0, 0, 0, 0, 0},
                      {3, 5, 0, 0, 0, 0, 0, 0, 0}};
        conv_mma<2, 0><<<dim3((32 * 33 + 127) / 128, 4, NB), 256>>>(
            xs, w1, t1, d1, nullptr, nullptr, nullptr, nullptr,
            HIN, HIN, 32, 33, bstride1, HT * HT, 2 * HT, 2, 1 * HT + 0, tp);
    }
    {   // phase (1,1): 1 tap
        TapList tp = {{0, 0, 0, 0, 0, 0, 0, 0, 0},
                      {0, 0, 0, 0, 0, 0, 0, 0, 0},
                      {4, 0, 0, 0, 0, 0, 0, 0, 0}};
        conv_mma<1, 0><<<dim3((32 * 32 + 127) / 128, 4, NB), 256>>>(
            xs, w1, t1, d1, nullptr, nullptr, nullptr, nullptr,
            HIN, HIN, 32, 32, bstride1, HT * HT, 2 * HT, 2, 1 * HT + 1, tp);
    }

    k_blur<<<dim3(NC, NB), 256>>>(t1, n1, nw1, b1, s2, a1);

    {   // conv2: 3x3 same, 9 taps
        TapList tp = {{-1, -1, -1, 0, 0, 0, 1, 1, 1},
                      {-1, 0, 1, -1, 0, 1, -1, 0, 1},
                      {0, 1, 2, 3, 4, 5, 6, 7, 8}};
        conv_mma<9, 1><<<dim3((HO * HO + 127) / 128, 4, NB), 256>>>(
            a1, w2, a2, d2, n2, nw2, b2, srgb,
            HO, HO, HO, HO, NC * HO * HO, HO * HO, HO, 1, 0, tp);
    }

    k_torgb<<<dim3(64, NB), 256>>>(a2, wrgb, brgb, skip, outp);
}

// round 5
// speedup vs baseline: 8.2244x; 5.1416x over previous
#include <cuda_runtime.h>
#include <math.h>
#include <stdint.h>

#define NB 8
#define NC 512
#define HIN 32
#define HT 65
#define HO 64

// ---------------- scratch (device globals; no allocations allowed) ----------
__device__ float    g_xs[NB * NC * HIN * HIN];  // style-scaled input (tf32-rounded)
__device__ float    g_t1[NB * NC * HT * HT];    // conv1 output 65x65 (fp32)
__device__ float    g_a1[NB * NC * HO * HO];    // blur+noise+lrelu*s2 (tf32-rounded)
__device__ float    g_a2[NB * NC * HO * HO];    // conv2 out *s_rgb (fp32)
__device__ float    g_d1[NB * NC];
__device__ float    g_d2[NB * NC];
__device__ uint32_t g_wt1[512 * 4608];          // w1 permuted [co][j*512+ci], tf32
__device__ uint32_t g_wt2[512 * 4608];          // w2 permuted, tf32

__device__ __forceinline__ uint32_t f2tf32(float x) {
    uint32_t r;
    asm("cvt.rna.tf32.f32 %0, %1;" : "=r"(r) : "f"(x));
    return r;
}

__device__ __forceinline__ void mma_tf32(float* d, const uint32_t* a, const uint32_t* b) {
    asm volatile(
        "mma.sync.aligned.m16n8k8.row.col.f32.tf32.tf32.f32 "
        "{%0,%1,%2,%3}, {%4,%5,%6,%7}, {%8,%9}, {%0,%1,%2,%3};\n"
        : "+f"(d[0]), "+f"(d[1]), "+f"(d[2]), "+f"(d[3])
        : "r"(a[0]), "r"(a[1]), "r"(a[2]), "r"(a[3]), "r"(b[0]), "r"(b[1]));
}

// ---------------- K_wperm: wt[co][j*512+ci] = tf32(w[co][ci*9+j]) ------------
__global__ void k_wperm(const float* __restrict__ w, uint32_t* __restrict__ wt) {
    __shared__ float row[4608];
    int co = blockIdx.x;
    const float* src = w + (size_t)co * 4608;
    for (int i = threadIdx.x; i < 4608; i += 256) row[i] = src[i];
    __syncthreads();
    uint32_t* dst = wt + (size_t)co * 4608;
    for (int m = threadIdx.x; m < 4608; m += 256) {
        int j = m >> 9, ci = m & 511;
        dst[m] = f2tf32(row[ci * 9 + j]);
    }
}

// ---------------- K0: demodulation factors ----------------------------------
__global__ void k_demod(const float* __restrict__ w, const float* __restrict__ s,
                        float* __restrict__ d, float scale) {
    int b  = blockIdx.x >> 9;
    int co = blockIdx.x & 511;
    const float* wr = w + co * 4608;
    const float* sr = s + b * 512;
    float acc = 0.f;
    for (int k = threadIdx.x; k < 4608; k += 128) {
        int ci = k / 9;
        float t = wr[k] * sr[ci];
        acc += t * t;
    }
    __shared__ float red[128];
    red[threadIdx.x] = acc;
    __syncthreads();
    for (int off = 64; off > 0; off >>= 1) {
        if (threadIdx.x < off) red[threadIdx.x] += red[threadIdx.x + off];
        __syncthreads();
    }
    if (threadIdx.x == 0)
        d[b * 512 + co] = scale * rsqrtf(scale * scale * red[0] + 1e-8f);
}

// ---------------- K_scale: xs = tf32(x * s1[b,c]) ----------------------------
__global__ void k_scale_x(const float* __restrict__ x, const float* __restrict__ s1,
                          float* __restrict__ xs) {
    int i = blockIdx.x * 256 + threadIdx.x;
    if (i < NB * NC * HIN * HIN) {
        int c = (i >> 10) & 511;
        int b = i >> 19;
        xs[i] = __uint_as_float(f2tf32(x[i] * s1[b * 512 + c]));
    }
}

// ---------------- implicit-GEMM conv on TF32 tensor cores -------------------
// Block 256(M=cout) x 128(N=pixels), BK=16, tap-major K. 8 warps 4x2, warp
// tile 64x64. A smem fragment-major (R4 layout, BM=256). B smem LDB=128 with
// XOR swizzle. Double-buffered, per-tap pipelines; tap scalars decoded from
// packed bitfields (no dynamic array indexing -> no local memory).
template <int NTAPS, int EPI>
__global__ __launch_bounds__(256, 1) void conv_mma(
    const float* __restrict__ in, const uint32_t* __restrict__ wt,
    float* __restrict__ out, const float* __restrict__ dmod,
    const float* __restrict__ noise, const float* __restrict__ nwp,
    const float* __restrict__ bias, const float* __restrict__ snext,
    int IH, int IW, int GH, int GW,
    int out_bstride, int out_cstride, int out_ys, int out_xs, int out_off,
    uint32_t pdy, uint32_t pdx, uint64_t pwo)
{
    __shared__ uint32_t As[2][4096];   // 2 k8 x 16 mblk x 128
    __shared__ uint32_t Bs[2][2048];   // 16 rows x 128, XOR-swizzled

    int tid  = threadIdx.x;
    int lane = tid & 31, warp = tid >> 5;
    int wm = warp >> 1, wn = warp & 1;   // 4(M) x 2(N) warp grid
    int kq = lane & 3, rq = lane >> 2;

    int b   = blockIdx.z;
    int co0 = blockIdx.y * 256;
    int n0  = blockIdx.x * 128;
    int GHW = GH * GW;
    int IHW = IH * IW;

    const float* inb = in + (size_t)b * 512 * IHW;

    // A loading: thread -> rows akm+16*l (l=0..15), k-local akk
    int akm = tid >> 4;
    int akk = tid & 15;
    const uint32_t* pA = wt + (size_t)(co0 + akm) * 4608 + akk;
    int a_st = (akk >> 3) * 2048 + (((akm & 7) * 4 + (akk & 3)) * 4)
             + (akm >> 3) + 2 * ((akk >> 2) & 1);

    // B loading: thread -> pixel nl, k rows bkl+2*l (l=0..7)
    int nl  = tid & 127;
    int bkl = tid >> 7;
    int ng  = n0 + nl;
    int oy, ox;
    if (ng < GHW) { oy = ng / GW; ox = ng - oy * GW; }
    else          { oy = -100000; ox = 0; }

    float acc[4][8][4];
#pragma unroll
    for (int i = 0; i < 4; i++)
#pragma unroll
        for (int j = 0; j < 8; j++)
#pragma unroll
            for (int r = 0; r < 4; r++) acc[i][j][r] = 0.f;

    uint32_t pa[16];
    float    pbv[8];

#pragma unroll 1
    for (int t = 0; t < NTAPS; t++) {
        int dy = (int)((pdy >> (2 * t)) & 3u) - 1;
        int dx = (int)((pdx >> (2 * t)) & 3u) - 1;
        int wo = (int)((pwo >> (4 * t)) & 15u);
        int iy = oy + dy, ix = ox + dx;
        bool bvalid = (iy >= 0) && (iy < IH) && (ix >= 0) && (ix < IW);
        const uint32_t* pAt = pA + wo * 512;
        const float*    pBt = inb + (size_t)bkl * IHW + iy * IW + ix;

        auto loadAB = [&](int kb2) {
            const uint32_t* pAk = pAt + kb2;
#pragma unroll
            for (int l = 0; l < 16; l++)
                pa[l] = pAk[(size_t)l * (16 * 4608)];
            const float* pBk = pBt + (size_t)kb2 * IHW;
#pragma unroll
            for (int l = 0; l < 8; l++) {
                float v = 0.f;
                if (bvalid) v = __ldg(pBk + (size_t)(2 * l) * IHW);
                pbv[l] = v;
            }
        };
        auto storeAB = [&](int st) {
#pragma unroll
            for (int l = 0; l < 16; l++) As[st][a_st + l * 128] = pa[l];
#pragma unroll
            for (int l = 0; l < 8; l++) {
                int k = bkl + 2 * l;
                Bs[st][k * 128 + (nl ^ ((k & 3) << 3))] = __float_as_uint(pbv[l]);
            }
        };

        loadAB(0);
        storeAB(0);
        __syncthreads();

#pragma unroll 2
        for (int it2 = 0; it2 < 32; it2++) {
            int st = it2 & 1;
            if (it2 < 31) loadAB((it2 + 1) * 16);

            const uint32_t* Ap = As[st];
            const uint32_t* Bp = Bs[st];
#pragma unroll
            for (int ks = 0; ks < 2; ks++) {
                uint32_t af[4][4], bf[8][2];
#pragma unroll
                for (int mt = 0; mt < 4; mt++) {
                    const uint4 v = *reinterpret_cast<const uint4*>(
                        &Ap[ks * 2048 + (wm * 4 + mt) * 128 + lane * 4]);
                    af[mt][0] = v.x; af[mt][1] = v.y; af[mt][2] = v.z; af[mt][3] = v.w;
                }
#pragma unroll
                for (int nt = 0; nt < 8; nt++) {
                    int cs = (wn * 64 + nt * 8 + rq) ^ (kq << 3);
                    bf[nt][0] = Bp[(ks * 8 + kq) * 128 + cs];
                    bf[nt][1] = Bp[(ks * 8 + kq + 4) * 128 + cs];
                }
#pragma unroll
                for (int mt = 0; mt < 4; mt++)
#pragma unroll
                    for (int nt = 0; nt < 8; nt++)
                        mma_tf32(acc[mt][nt], af[mt], bf[nt]);
            }

            if (it2 < 31) storeAB(st ^ 1);
            __syncthreads();
        }
    }

    // ---- epilogue ----
    const float SQRT2 = 1.41421356237309515f;
    float* outb = out + (size_t)b * out_bstride;
    float nwv = (EPI == 1) ? nwp[0] : 0.f;
    int mbase = wm * 64, nbase = wn * 64;
#pragma unroll
    for (int mt = 0; mt < 4; mt++) {
#pragma unroll
        for (int half = 0; half < 2; half++) {
            int co = co0 + mbase + mt * 16 + rq + half * 8;
            float dm = dmod[b * 512 + co];
            float bi = (EPI == 1) ? bias[co] : 0.f;
            float sn = (EPI == 1) ? snext[b * 512 + co] : 0.f;
#pragma unroll
            for (int nt = 0; nt < 8; nt++) {
#pragma unroll
                for (int j = 0; j < 2; j++) {
                    int n = n0 + nbase + nt * 8 + kq * 2 + j;
                    if (n < GHW) {
                        int oyp = n / GW;
                        int oxp = n - oyp * GW;
                        float v = acc[mt][nt][half * 2 + j] * dm;
                        if (EPI == 1) {
                            v += nwv * noise[b * GHW + n] + bi;
                            v = (v >= 0.f ? v : 0.2f * v) * SQRT2;
                            v *= sn;
                        }
                        outb[(size_t)co * out_cstride + oyp * out_ys + oxp * out_xs + out_off] = v;
                    }
                }
            }
        }
    }
}

// ---------------- K2: blur 4x4 (separable, smem) + noise + lrelu + s2 -------
__global__ __launch_bounds__(256) void k_blur(
    const float* __restrict__ t1, const float* __restrict__ n1,
    const float* __restrict__ nw1, const float* __restrict__ b1,
    const float* __restrict__ s2, float* __restrict__ a1)
{
    __shared__ float raw[67 * 68];
    __shared__ float tmp[67 * 64];
    int tid = threadIdx.x;
    int c = blockIdx.x, b = blockIdx.y;
    const float* tb = t1 + (size_t)(b * 512 + c) * (HT * HT);

    for (int i = tid; i < 67 * 67; i += 256) {
        int rr = i / 67, cc = i - rr * 67;
        int ty = rr - 1, tx = cc - 1;
        float v = 0.f;
        if (ty >= 0 && ty < HT && tx >= 0 && tx < HT) v = tb[ty * HT + tx];
        raw[rr * 68 + cc] = v;
    }
    __syncthreads();

    for (int i = tid; i < 67 * 64; i += 256) {
        int r = i >> 6, x = i & 63;
        const float* rp = &raw[r * 68 + x];
        tmp[i] = rp[0] + 3.f * rp[1] + 3.f * rp[2] + rp[3];
    }
    __syncthreads();

    float nwv = nw1[0];
    float bi  = b1[c];
    float s2v = s2[b * 512 + c];
    float* ap = a1 + (size_t)(b * 512 + c) * 4096;
    const float* np = n1 + (size_t)b * 4096;
    for (int pix = tid; pix < 4096; pix += 256) {
        int y = pix >> 6, x = pix & 63;
        float acc = tmp[y * 64 + x] + 3.f * tmp[(y + 1) * 64 + x]
                  + 3.f * tmp[(y + 2) * 64 + x] + tmp[(y + 3) * 64 + x];
        acc *= (1.f / 16.f);
        float v = acc + nwv * np[pix] + bi;
        v = (v >= 0.f ? v : 0.2f * v) * 1.41421356237309515f;
        ap[pix] = __uint_as_float(f2tf32(v * s2v));
    }
}

// ---------------- K4: ToRGB + bias + skip upfirdn up=2 ----------------------
__global__ void k_torgb(const float* __restrict__ a2, const float* __restrict__ wrgb,
                        const float* __restrict__ brgb, const float* __restrict__ skip,
                        float* __restrict__ outp) {
    __shared__ float sw[1536];
    __shared__ float red[3][256];
    int tid = threadIdx.x;
    int b = blockIdx.y;
    const float srgb = 0.044194173824159216f;  // 1/sqrt(512)
    for (int i = tid; i < 1536; i += 256) sw[i] = wrgb[i] * srgb;
    __syncthreads();

    int p = tid & 63;
    int g = tid >> 6;
    int pix = blockIdx.x * 64 + p;
    const float* ab = a2 + (size_t)b * 512 * 4096 + pix;
    float acc0 = 0.f, acc1 = 0.f, acc2 = 0.f;
#pragma unroll 8
    for (int c = g * 128; c < g * 128 + 128; c++) {
        float v = ab[(size_t)c * 4096];
        acc0 += sw[c] * v;
        acc1 += sw[512 + c] * v;
        acc2 += sw[1024 + c] * v;
    }
    red[0][tid] = acc0; red[1][tid] = acc1; red[2][tid] = acc2;
    __syncthreads();

    if (g == 0) {
        int y = pix >> 6, x = pix & 63;
        int iy0, iy1, ix0, ix1;
        float wy0, wy1, wx0, wx1;
        if ((y & 1) == 0) { iy0 = y / 2 - 1;   wy0 = 1.f; iy1 = y / 2;       wy1 = 3.f; }
        else              { iy0 = (y - 1) / 2; wy0 = 3.f; iy1 = (y + 1) / 2; wy1 = 1.f; }
        if ((x & 1) == 0) { ix0 = x / 2 - 1;   wx0 = 1.f; ix1 = x / 2;       wx1 = 3.f; }
        else              { ix0 = (x - 1) / 2; wx0 = 3.f; ix1 = (x + 1) / 2; wx1 = 1.f; }

#pragma unroll
        for (int o = 0; o < 3; o++) {
            float acc = red[o][p] + red[o][p + 64] + red[o][p + 128] + red[o][p + 192];
            const float* sb = skip + (size_t)(b * 3 + o) * 1024;
            float s = 0.f;
            if (iy0 >= 0 && iy0 < 32) {
                if (ix0 >= 0 && ix0 < 32) s += sb[iy0 * 32 + ix0] * wy0 * wx0;
                if (ix1 >= 0 && ix1 < 32) s += sb[iy0 * 32 + ix1] * wy0 * wx1;
            }
            if (iy1 >= 0 && iy1 < 32) {
                if (ix0 >= 0 && ix0 < 32) s += sb[iy1 * 32 + ix0] * wy1 * wx0;
                if (ix1 >= 0 && ix1 < 32) s += sb[iy1 * 32 + ix1] * wy1 * wx1;
            }
            s *= (1.f / 16.f);
            outp[(size_t)(b * 3 + o) * 4096 + pix] = acc + brgb[o] + s;
        }
    }
}

// ---------------- host-side tap packing --------------------------------------
static void pack_taps(const int* dy, const int* dx, const int* wo, int n,
                      uint32_t& pdy, uint32_t& pdx, uint64_t& pwo) {
    pdy = 0; pdx = 0; pwo = 0;
    for (int t = 0; t < n; t++) {
        pdy |= (uint32_t)(dy[t] + 1) << (2 * t);
        pdx |= (uint32_t)(dx[t] + 1) << (2 * t);
        pwo |= (uint64_t)(wo[t]) << (4 * t);
    }
}

// ---------------- launch -----------------------------------------------------
extern "C" void kernel_launch(void* const* d_in, const int* in_sizes, int n_in,
                              void* d_out, int out_size) {
    const float* x    = (const float*)d_in[0];
    const float* skip = (const float*)d_in[1];
    const float* w1   = (const float*)d_in[2];
    const float* b1   = (const float*)d_in[3];
    const float* s1   = (const float*)d_in[4];
    const float* nw1  = (const float*)d_in[5];
    const float* n1   = (const float*)d_in[6];
    const float* w2   = (const float*)d_in[7];
    const float* b2   = (const float*)d_in[8];
    const float* s2   = (const float*)d_in[9];
    const float* nw2  = (const float*)d_in[10];
    const float* n2   = (const float*)d_in[11];
    const float* wrgb = (const float*)d_in[12];
    const float* brgb = (const float*)d_in[13];
    const float* srgb = (const float*)d_in[14];
    float* outp = (float*)d_out;

    float *xs, *t1, *a1, *a2, *d1, *d2;
    uint32_t *wt1, *wt2;
    cudaGetSymbolAddress((void**)&xs, g_xs);
    cudaGetSymbolAddress((void**)&t1, g_t1);
    cudaGetSymbolAddress((void**)&a1, g_a1);
    cudaGetSymbolAddress((void**)&a2, g_a2);
    cudaGetSymbolAddress((void**)&d1, g_d1);
    cudaGetSymbolAddress((void**)&d2, g_d2);
    cudaGetSymbolAddress((void**)&wt1, g_wt1);
    cudaGetSymbolAddress((void**)&wt2, g_wt2);

    const float sc = 1.0f / sqrtf(512.0f * 9.0f);

    k_wperm<<<512, 256>>>(w1, wt1);
    k_wperm<<<512, 256>>>(w2, wt2);
    k_scale_x<<<(NB * NC * HIN * HIN + 255) / 256, 256>>>(x, s1, xs);
    k_demod<<<NB * NC, 128>>>(w1, s1, d1, sc);
    k_demod<<<NB * NC, 128>>>(w2, s2, d2, sc);

    int bstride1 = NC * HT * HT;
    uint32_t pdy, pdx; uint64_t pwo;

    {   // phase (0,0): 4 taps, grid 33x33
        int dy[4] = {0, 0, -1, -1}, dx[4] = {0, -1, 0, -1}, wo[4] = {0, 2, 6, 8};
        pack_taps(dy, dx, wo, 4, pdy, pdx, pwo);
        conv_mma<4, 0><<<dim3((33 * 33 + 127) / 128, 2, NB), 256>>>(
            xs, wt1, t1, d1, nullptr, nullptr, nullptr, nullptr,
            HIN, HIN, 33, 33, bstride1, HT * HT, 2 * HT, 2, 0 * HT + 0, pdy, pdx, pwo);
    }
    {   // phase (0,1): 2 taps
        int dy[2] = {0, -1}, dx[2] = {0, 0}, wo[2] = {1, 7};
        pack_taps(dy, dx, wo, 2, pdy, pdx, pwo);
        conv_mma<2, 0><<<dim3((33 * 32 + 127) / 128, 2, NB), 256>>>(
            xs, wt1, t1, d1, nullptr, nullptr, nullptr, nullptr,
            HIN, HIN, 33, 32, bstride1, HT * HT, 2 * HT, 2, 0 * HT + 1, pdy, pdx, pwo);
    }
    {   // phase (1,0): 2 taps
        int dy[2] = {0, 0}, dx[2] = {0, -1}, wo[2] = {3, 5};
        pack_taps(dy, dx, wo, 2, pdy, pdx, pwo);
        conv_mma<2, 0><<<dim3((32 * 33 + 127) / 128, 2, NB), 256>>>(
            xs, wt1, t1, d1, nullptr, nullptr, nullptr, nullptr,
            HIN, HIN, 32, 33, bstride1, HT * HT, 2 * HT, 2, 1 * HT + 0, pdy, pdx, pwo);
    }
    {   // phase (1,1): 1 tap
        int dy[1] = {0}, dx[1] = {0}, wo[1] = {4};
        pack_taps(dy, dx, wo, 1, pdy, pdx, pwo);
        conv_mma<1, 0><<<dim3((32 * 32 + 127) / 128, 2, NB), 256>>>(
            xs, wt1, t1, d1, nullptr, nullptr, nullptr, nullptr,
            HIN, HIN, 32, 32, bstride1, HT * HT, 2 * HT, 2, 1 * HT + 1, pdy, pdx, pwo);
    }

    k_blur<<<dim3(NC, NB), 256>>>(t1, n1, nw1, b1, s2, a1);

    {   // conv2: 3x3 same, 9 taps
        int dy[9], dx[9], wo[9];
        for (int t = 0; t < 9; t++) { dy[t] = t / 3 - 1; dx[t] = t % 3 - 1; wo[t] = t; }
        pack_taps(dy, dx, wo, 9, pdy, pdx, pwo);
        conv_mma<9, 1><<<dim3((HO * HO + 127) / 128, 2, NB), 256>>>(
            a1, wt2, a2, d2, n2, nw2, b2, srgb,
            HO, HO, HO, HO, NC * HO * HO, HO * HO, HO, 1, 0, pdy, pdx, pwo);
    }

    k_torgb<<<dim3(64, NB), 256>>>(a2, wrgb, brgb, skip, outp);
}

// round 6
// speedup vs baseline: 8.4505x; 1.0275x over previous
#include <cuda_runtime.h>
#include <math.h>
#include <stdint.h>

#define NB 8
#define NC 512
#define HIN 32
#define HT 65
#define HO 64

// ---------------- scratch (device globals; no allocations allowed) ----------
__device__ float    g_xs[NB * NC * HIN * HIN];  // style-scaled input (tf32-rounded)
__device__ float    g_t1[NB * NC * HT * HT];    // conv1 output 65x65 (fp32)
__device__ float    g_a1[NB * NC * HO * HO];    // blur+noise+lrelu*s2 (tf32-rounded)
__device__ float    g_a2[NB * NC * HO * HO];    // conv2 out *s_rgb (fp32)
__device__ float    g_d1[NB * NC];
__device__ float    g_d2[NB * NC];
__device__ uint32_t g_wt1[512 * 4608];          // w1 permuted [co][j*512+ci], tf32
__device__ uint32_t g_wt2[512 * 4608];          // w2 permuted, tf32
__device__ float    g_w2a[512 * 512];           // sum_j w1[co,ci,j]^2
__device__ float    g_w2b[512 * 512];           // sum_j w2[co,ci,j]^2

__device__ __forceinline__ uint32_t f2tf32(float x) {
    uint32_t r;
    asm("cvt.rna.tf32.f32 %0, %1;" : "=r"(r) : "f"(x));
    return r;
}

__device__ __forceinline__ void mma_tf32(float* d, const uint32_t* a, const uint32_t* b) {
    asm volatile(
        "mma.sync.aligned.m16n8k8.row.col.f32.tf32.tf32.f32 "
        "{%0,%1,%2,%3}, {%4,%5,%6,%7}, {%8,%9}, {%0,%1,%2,%3};\n"
        : "+f"(d[0]), "+f"(d[1]), "+f"(d[2]), "+f"(d[3])
        : "r"(a[0]), "r"(a[1]), "r"(a[2]), "r"(a[3]), "r"(b[0]), "r"(b[1]));
}

// ---------------- K_wperm: wt[co][j*512+ci] = tf32(w[co][ci*9+j]); W2 row ----
__global__ void k_wperm(const float* __restrict__ w, uint32_t* __restrict__ wt,
                        float* __restrict__ w2s) {
    __shared__ float row[4608];
    int co = blockIdx.x;
    const float* src = w + (size_t)co * 4608;
    for (int i = threadIdx.x; i < 4608; i += 256) row[i] = src[i];
    __syncthreads();
    uint32_t* dst = wt + (size_t)co * 4608;
    for (int m = threadIdx.x; m < 4608; m += 256) {
        int j = m >> 9, ci = m & 511;
        dst[m] = f2tf32(row[ci * 9 + j]);
    }
    for (int ci = threadIdx.x; ci < 512; ci += 256) {
        float s = 0.f;
#pragma unroll
        for (int j = 0; j < 9; j++) { float t = row[ci * 9 + j]; s += t * t; }
        w2s[(size_t)co * 512 + ci] = s;
    }
}

// ---------------- K_demod2: d[b,co] = sc*rsqrt(sc^2*sum W2[co,ci]*s^2 + eps) -
__global__ void k_demod2(const float* __restrict__ w2s, const float* __restrict__ s,
                         float* __restrict__ d, float scale) {
    int warp = threadIdx.x >> 5, lane = threadIdx.x & 31;
    int gid = blockIdx.x * 8 + warp;          // 0..4095
    int b = gid >> 9, co = gid & 511;
    const float* wr = w2s + (size_t)co * 512;
    const float* sr = s + b * 512;
    float acc = 0.f;
#pragma unroll
    for (int i = lane; i < 512; i += 32) {
        float sv = sr[i];
        acc += wr[i] * sv * sv;
    }
#pragma unroll
    for (int off = 16; off > 0; off >>= 1)
        acc += __shfl_xor_sync(0xFFFFFFFFu, acc, off);
    if (lane == 0)
        d[b * 512 + co] = scale * rsqrtf(scale * scale * acc + 1e-8f);
}

// ---------------- K_scale: xs = tf32(x * s1[b,c]) ----------------------------
__global__ void k_scale_x(const float* __restrict__ x, const float* __restrict__ s1,
                          float* __restrict__ xs) {
    int i = blockIdx.x * 256 + threadIdx.x;
    if (i < NB * NC * HIN * HIN) {
        int c = (i >> 10) & 511;
        int b = i >> 19;
        xs[i] = __uint_as_float(f2tf32(x[i] * s1[b * 512 + c]));
    }
}

// ---------------- implicit-GEMM conv on TF32 tensor cores -------------------
// Block 256(M) x 128(N), BK=16, 512 threads, warp grid 4x4, warp tile 64x32.
// A smem fragment-major (LDS.128 frag loads). B smem fragment-major with
// rotation swizzle (+2*nblk within tile) -> LDS.64 frag loads, conflict-free
// stores. Double-buffered, tap-major K.
template <int NTAPS, int EPI>
__global__ __launch_bounds__(512, 1) void conv_mma(
    const float* __restrict__ in, const uint32_t* __restrict__ wt,
    float* __restrict__ out, const float* __restrict__ dmod,
    const float* __restrict__ noise, const float* __restrict__ nwp,
    const float* __restrict__ bias, const float* __restrict__ snext,
    int IH, int IW, int GH, int GW,
    int out_bstride, int out_cstride, int out_ys, int out_xs, int out_off,
    uint32_t pdy, uint32_t pdx, uint64_t pwo)
{
    __shared__ uint32_t As[2][4096];   // 2 k8 x 16 mblk x 128  (32 KB)
    __shared__ uint32_t Bs[2][2048];   // 32 tiles x 64, frag-major (16 KB)

    int tid  = threadIdx.x;
    int lane = tid & 31, warp = tid >> 5;
    int wm = warp >> 2, wn = warp & 3;   // 4(M) x 4(N) warp grid
    int kq = lane & 3, rq = lane >> 2;

    int b   = blockIdx.z;
    int co0 = blockIdx.y * 256;
    int n0  = blockIdx.x * 128;
    int GHW = GH * GW;
    int IHW = IH * IW;

    const float* inb = in + (size_t)b * 512 * IHW;

    // A loading: thread -> rows akm+32*l (l=0..7), k-local akk
    int akm = tid >> 4;                  // 0..31
    int akk = tid & 15;
    const uint32_t* pA = wt + (size_t)(co0 + akm) * 4608 + akk;
    int a_st = (akk >> 3) * 2048 + (akm >> 4) * 128
             + (((akm & 7) * 4 + (akk & 3)) * 4)
             + ((akm >> 3) & 1) + 2 * ((akk >> 2) & 1);

    // B loading: thread -> pixel nl, k rows bkl+4*l (l=0..3)
    int nl  = tid & 127;
    int bkl = tid >> 7;                  // 0..3
    int ng  = n0 + nl;
    int oy, ox;
    if (ng < GHW) { oy = ng / GW; ox = ng - oy * GW; }
    else          { oy = -100000; ox = 0; }
    int b_nblk = nl >> 3, b_rqb = nl & 7;

    float acc[4][4][4];
#pragma unroll
    for (int i = 0; i < 4; i++)
#pragma unroll
        for (int j = 0; j < 4; j++)
#pragma unroll
            for (int r = 0; r < 4; r++) acc[i][j][r] = 0.f;

    uint32_t pa[8];
    float    pbv[4];

#pragma unroll 1
    for (int t = 0; t < NTAPS; t++) {
        int dy = (int)((pdy >> (2 * t)) & 3u) - 1;
        int dx = (int)((pdx >> (2 * t)) & 3u) - 1;
        int wo = (int)((pwo >> (4 * t)) & 15u);
        int iy = oy + dy, ix = ox + dx;
        bool bvalid = (iy >= 0) && (iy < IH) && (ix >= 0) && (ix < IW);
        const uint32_t* pAt = pA + wo * 512;
        const float*    pBt = inb + iy * IW + ix;

        auto loadAB = [&](int kb2) {
            const uint32_t* pAk = pAt + kb2;
#pragma unroll
            for (int l = 0; l < 8; l++)
                pa[l] = pAk[(size_t)l * (32 * 4608)];
            const float* pBk = pBt + (size_t)(kb2 + bkl) * IHW;
#pragma unroll
            for (int l = 0; l < 4; l++) {
                float v = 0.f;
                if (bvalid) v = __ldg(pBk + (size_t)(4 * l) * IHW);
                pbv[l] = v;
            }
        };
        auto storeAB = [&](int st) {
#pragma unroll
            for (int l = 0; l < 8; l++) As[st][a_st + l * 256] = pa[l];
#pragma unroll
            for (int l = 0; l < 4; l++) {
                int k = bkl + 4 * l;
                int ks = k >> 3, kqv = k & 3, e = (k >> 2) & 1;
                int intra = (((b_rqb * 4 + kqv) * 2 + e) + 2 * b_nblk) & 63;
                Bs[st][(ks * 16 + b_nblk) * 64 + intra] = __float_as_uint(pbv[l]);
            }
        };

        loadAB(0);
        storeAB(0);
        __syncthreads();

#pragma unroll 2
        for (int it2 = 0; it2 < 32; it2++) {
            int st = it2 & 1;
            if (it2 < 31) loadAB((it2 + 1) * 16);

            const uint32_t* Ap = As[st];
            const uint32_t* Bp = Bs[st];
#pragma unroll
            for (int ks = 0; ks < 2; ks++) {
                uint32_t af[4][4], bf[4][2];
#pragma unroll
                for (int mt = 0; mt < 4; mt++) {
                    const uint4 v = *reinterpret_cast<const uint4*>(
                        &Ap[ks * 2048 + (wm * 4 + mt) * 128 + lane * 4]);
                    af[mt][0] = v.x; af[mt][1] = v.y; af[mt][2] = v.z; af[mt][3] = v.w;
                }
#pragma unroll
                for (int nt = 0; nt < 4; nt++) {
                    int nblk = wn * 4 + nt;
                    int off = ((lane * 2) + 2 * nblk) & 63;
                    const uint2 v = *reinterpret_cast<const uint2*>(
                        &Bp[(ks * 16 + nblk) * 64 + off]);
                    bf[nt][0] = v.x; bf[nt][1] = v.y;
                }
#pragma unroll
                for (int mt = 0; mt < 4; mt++)
#pragma unroll
                    for (int nt = 0; nt < 4; nt++)
                        mma_tf32(acc[mt][nt], af[mt], bf[nt]);
            }

            if (it2 < 31) storeAB(st ^ 1);
            __syncthreads();
        }
    }

    // ---- epilogue ----
    const float SQRT2 = 1.41421356237309515f;
    float* outb = out + (size_t)b * out_bstride;
    float nwv = (EPI == 1) ? nwp[0] : 0.f;
    int mbase = wm * 64, nbase = wn * 32;
#pragma unroll
    for (int mt = 0; mt < 4; mt++) {
#pragma unroll
        for (int half = 0; half < 2; half++) {
            int co = co0 + mbase + mt * 16 + rq + half * 8;
            float dm = dmod[b * 512 + co];
            float bi = (EPI == 1) ? bias[co] : 0.f;
            float sn = (EPI == 1) ? snext[b * 512 + co] : 0.f;
#pragma unroll
            for (int nt = 0; nt < 4; nt++) {
#pragma unroll
                for (int j = 0; j < 2; j++) {
                    int n = n0 + nbase + nt * 8 + kq * 2 + j;
                    if (n < GHW) {
                        int oyp = n / GW;
                        int oxp = n - oyp * GW;
                        float v = acc[mt][nt][half * 2 + j] * dm;
                        if (EPI == 1) {
                            v += nwv * noise[b * GHW + n] + bi;
                            v = (v >= 0.f ? v : 0.2f * v) * SQRT2;
                            v *= sn;
                        }
                        outb[(size_t)co * out_cstride + oyp * out_ys + oxp * out_xs + out_off] = v;
                    }
                }
            }
        }
    }
}

// ---------------- K2: blur 4x4 (separable, smem) + noise + lrelu + s2 -------
__global__ __launch_bounds__(256) void k_blur(
    const float* __restrict__ t1, const float* __restrict__ n1,
    const float* __restrict__ nw1, const float* __restrict__ b1,
    const float* __restrict__ s2, float* __restrict__ a1)
{
    __shared__ float raw[67 * 68];
    __shared__ float tmp[67 * 64];
    int tid = threadIdx.x;
    int c = blockIdx.x, b = blockIdx.y;
    const float* tb = t1 + (size_t)(b * 512 + c) * (HT * HT);

    for (int i = tid; i < 67 * 67; i += 256) {
        int rr = i / 67, cc = i - rr * 67;
        int ty = rr - 1, tx = cc - 1;
        float v = 0.f;
        if (ty >= 0 && ty < HT && tx >= 0 && tx < HT) v = tb[ty * HT + tx];
        raw[rr * 68 + cc] = v;
    }
    __syncthreads();

    for (int i = tid; i < 67 * 64; i += 256) {
        int r = i >> 6, x = i & 63;
        const float* rp = &raw[r * 68 + x];
        tmp[i] = rp[0] + 3.f * rp[1] + 3.f * rp[2] + rp[3];
    }
    __syncthreads();

    float nwv = nw1[0];
    float bi  = b1[c];
    float s2v = s2[b * 512 + c];
    float* ap = a1 + (size_t)(b * 512 + c) * 4096;
    const float* np = n1 + (size_t)b * 4096;
    for (int pix = tid; pix < 4096; pix += 256) {
        int y = pix >> 6, x = pix & 63;
        float acc = tmp[y * 64 + x] + 3.f * tmp[(y + 1) * 64 + x]
                  + 3.f * tmp[(y + 2) * 64 + x] + tmp[(y + 3) * 64 + x];
        acc *= (1.f / 16.f);
        float v = acc + nwv * np[pix] + bi;
        v = (v >= 0.f ? v : 0.2f * v) * 1.41421356237309515f;
        ap[pix] = __uint_as_float(f2tf32(v * s2v));
    }
}

// ---------------- K4: ToRGB + bias + skip upfirdn up=2 ----------------------
__global__ void k_torgb(const float* __restrict__ a2, const float* __restrict__ wrgb,
                        const float* __restrict__ brgb, const float* __restrict__ skip,
                        float* __restrict__ outp) {
    __shared__ float sw[1536];
    __shared__ float red[3][256];
    int tid = threadIdx.x;
    int b = blockIdx.y;
    const float srgb = 0.044194173824159216f;  // 1/sqrt(512)
    for (int i = tid; i < 1536; i += 256) sw[i] = wrgb[i] * srgb;
    __syncthreads();

    int p = tid & 63;
    int g = tid >> 6;
    int pix = blockIdx.x * 64 + p;
    const float* ab = a2 + (size_t)b * 512 * 4096 + pix;
    float acc0 = 0.f, acc1 = 0.f, acc2 = 0.f;
#pragma unroll 8
    for (int c = g * 128; c < g * 128 + 128; c++) {
        float v = ab[(size_t)c * 4096];
        acc0 += sw[c] * v;
        acc1 += sw[512 + c] * v;
        acc2 += sw[1024 + c] * v;
    }
    red[0][tid] = acc0; red[1][tid] = acc1; red[2][tid] = acc2;
    __syncthreads();

    if (g == 0) {
        int y = pix >> 6, x = pix & 63;
        int iy0, iy1, ix0, ix1;
        float wy0, wy1, wx0, wx1;
        if ((y & 1) == 0) { iy0 = y / 2 - 1;   wy0 = 1.f; iy1 = y / 2;       wy1 = 3.f; }
        else              { iy0 = (y - 1) / 2; wy0 = 3.f; iy1 = (y + 1) / 2; wy1 = 1.f; }
        if ((x & 1) == 0) { ix0 = x / 2 - 1;   wx0 = 1.f; ix1 = x / 2;       wx1 = 3.f; }
        else              { ix0 = (x - 1) / 2; wx0 = 3.f; ix1 = (x + 1) / 2; wx1 = 1.f; }

#pragma unroll
        for (int o = 0; o < 3; o++) {
            float acc = red[o][p] + red[o][p + 64] + red[o][p + 128] + red[o][p + 192];
            const float* sb = skip + (size_t)(b * 3 + o) * 1024;
            float s = 0.f;
            if (iy0 >= 0 && iy0 < 32) {
                if (ix0 >= 0 && ix0 < 32) s += sb[iy0 * 32 + ix0] * wy0 * wx0;
                if (ix1 >= 0 && ix1 < 32) s += sb[iy0 * 32 + ix1] * wy0 * wx1;
            }
            if (iy1 >= 0 && iy1 < 32) {
                if (ix0 >= 0 && ix0 < 32) s += sb[iy1 * 32 + ix0] * wy1 * wx0;
                if (ix1 >= 0 && ix1 < 32) s += sb[iy1 * 32 + ix1] * wy1 * wx1;
            }
            s *= (1.f / 16.f);
            outp[(size_t)(b * 3 + o) * 4096 + pix] = acc + brgb[o] + s;
        }
    }
}

// ---------------- host-side tap packing --------------------------------------
static void pack_taps(const int* dy, const int* dx, const int* wo, int n,
                      uint32_t& pdy, uint32_t& pdx, uint64_t& pwo) {
    pdy = 0; pdx = 0; pwo = 0;
    for (int t = 0; t < n; t++) {
        pdy |= (uint32_t)(dy[t] + 1) << (2 * t);
        pdx |= (uint32_t)(dx[t] + 1) << (2 * t);
        pwo |= (uint64_t)(wo[t]) << (4 * t);
    }
}

// ---------------- launch -----------------------------------------------------
extern "C" void kernel_launch(void* const* d_in, const int* in_sizes, int n_in,
                              void* d_out, int out_size) {
    const float* x    = (const float*)d_in[0];
    const float* skip = (const float*)d_in[1];
    const float* w1   = (const float*)d_in[2];
    const float* b1   = (const float*)d_in[3];
    const float* s1   = (const float*)d_in[4];
    const float* nw1  = (const float*)d_in[5];
    const float* n1   = (const float*)d_in[6];
    const float* w2   = (const float*)d_in[7];
    const float* b2   = (const float*)d_in[8];
    const float* s2   = (const float*)d_in[9];
    const float* nw2  = (const float*)d_in[10];
    const float* n2   = (const float*)d_in[11];
    const float* wrgb = (const float*)d_in[12];
    const float* brgb = (const float*)d_in[13];
    const float* srgb = (const float*)d_in[14];
    float* outp = (float*)d_out;

    float *xs, *t1, *a1, *a2, *d1, *d2, *w2a, *w2b;
    uint32_t *wt1, *wt2;
    cudaGetSymbolAddress((void**)&xs, g_xs);
    cudaGetSymbolAddress((void**)&t1, g_t1);
    cudaGetSymbolAddress((void**)&a1, g_a1);
    cudaGetSymbolAddress((void**)&a2, g_a2);
    cudaGetSymbolAddress((void**)&d1, g_d1);
    cudaGetSymbolAddress((void**)&d2, g_d2);
    cudaGetSymbolAddress((void**)&wt1, g_wt1);
    cudaGetSymbolAddress((void**)&wt2, g_wt2);
    cudaGetSymbolAddress((void**)&w2a, g_w2a);
    cudaGetSymbolAddress((void**)&w2b, g_w2b);

    const float sc = 1.0f / sqrtf(512.0f * 9.0f);

    k_wperm<<<512, 256>>>(w1, wt1, w2a);
    k_wperm<<<512, 256>>>(w2, wt2, w2b);
    k_scale_x<<<(NB * NC * HIN * HIN + 255) / 256, 256>>>(x, s1, xs);
    k_demod2<<<512, 256>>>(w2a, s1, d1, sc);
    k_demod2<<<512, 256>>>(w2b, s2, d2, sc);

    int bstride1 = NC * HT * HT;
    uint32_t pdy, pdx; uint64_t pwo;

    {   // phase (0,0): 4 taps, grid 33x33
        int dy[4] = {0, 0, -1, -1}, dx[4] = {0, -1, 0, -1}, wo[4] = {0, 2, 6, 8};
        pack_taps(dy, dx, wo, 4, pdy, pdx, pwo);
        conv_mma<4, 0><<<dim3((33 * 33 + 127) / 128, 2, NB), 512>>>(
            xs, wt1, t1, d1, nullptr, nullptr, nullptr, nullptr,
            HIN, HIN, 33, 33, bstride1, HT * HT, 2 * HT, 2, 0 * HT + 0, pdy, pdx, pwo);
    }
    {   // phase (0,1): 2 taps
        int dy[2] = {0, -1}, dx[2] = {0, 0}, wo[2] = {1, 7};
        pack_taps(dy, dx, wo, 2, pdy, pdx, pwo);
        conv_mma<2, 0><<<dim3((33 * 32 + 127) / 128, 2, NB), 512>>>(
            xs, wt1, t1, d1, nullptr, nullptr, nullptr, nullptr,
            HIN, HIN, 33, 32, bstride1, HT * HT, 2 * HT, 2, 0 * HT + 1, pdy, pdx, pwo);
    }
    {   // phase (1,0): 2 taps
        int dy[2] = {0, 0}, dx[2] = {0, -1}, wo[2] = {3, 5};
        pack_taps(dy, dx, wo, 2, pdy, pdx, pwo);
        conv_mma<2, 0><<<dim3((32 * 33 + 127) / 128, 2, NB), 512>>>(
            xs, wt1, t1, d1, nullptr, nullptr, nullptr, nullptr,
            HIN, HIN, 32, 33, bstride1, HT * HT, 2 * HT, 2, 1 * HT + 0, pdy, pdx, pwo);
    }
    {   // phase (1,1): 1 tap
        int dy[1] = {0}, dx[1] = {0}, wo[1] = {4};
        pack_taps(dy, dx, wo, 1, pdy, pdx, pwo);
        conv_mma<1, 0><<<dim3((32 * 32 + 127) / 128, 2, NB), 512>>>(
            xs, wt1, t1, d1, nullptr, nullptr, nullptr, nullptr,
            HIN, HIN, 32, 32, bstride1, HT * HT, 2 * HT, 2, 1 * HT + 1, pdy, pdx, pwo);
    }

    k_blur<<<dim3(NC, NB), 256>>>(t1, n1, nw1, b1, s2, a1);

    {   // conv2: 3x3 same, 9 taps
        int dy[9], dx[9], wo[9];
        for (int t = 0; t < 9; t++) { dy[t] = t / 3 - 1; dx[t] = t % 3 - 1; wo[t] = t; }
        pack_taps(dy, dx, wo, 9, pdy, pdx, pwo);
        conv_mma<9, 1><<<dim3((HO * HO + 127) / 128, 2, NB), 512>>>(
            a1, wt2, a2, d2, n2, nw2, b2, srgb,
            HO, HO, HO, HO, NC * HO * HO, HO * HO, HO, 1, 0, pdy, pdx, pwo);
    }

    k_torgb<<<dim3(64, NB), 256>>>(a2, wrgb, brgb, skip, outp);
}